// round 13
// baseline (speedup 1.0000x reference)
#include <cuda_runtime.h>
#include <cuda_fp16.h>
#include <cstdint>

#define H     128
#define NENT  40000
#define NREL  256
#define NJ    129     // 129 att-intervals (128 breakpoints)
#define TMAX  10241
#define SPB   4       // segments per kedge block
#define MTILE 128

// ---------------- scratch (device globals; no allocation) ----------------
// PLANAR rows (512B each): [P3 halfs x128 | P4 halfs x128]; AC: [A x128 | C x128]
__device__ __half g_Ps[(NENT + MTILE) * 256];
__device__ __half g_Pr[NREL * 256];
__device__ __half g_AC[NJ * 256];
__device__ float  g_thr[H];                  // sorted breakpoints
__device__ int    g_off[TMAX];               // segment start offsets
// B in tf32, pre-packed in per-lane mma-fragment order:
__device__ float  g_Bp[2][2][16 * 8 * 32 * 4];

__device__ __forceinline__ uint32_t f2tf(float x) {
    uint32_t r;
    asm("cvt.rna.tf32.f32 %0, %1;" : "=r"(r) : "f"(x));
    return r;
}

// ---------------- K0: fused setup (NJ=129 blocks x 128 threads) ----------------
__device__ __forceinline__ void bput(int mat, int k, int n, float x) {
    int nh = n >> 7, nl = n & 127;
    int g = nl & 7, nt = nl >> 3;
    int kk = k >> 3, r = k & 7;
    int b = (r >= 4) ? 1 : 0, t = r & 3;
    int lane = (g << 2) | t;
    int j4 = nt >> 1, c = ((nt & 1) << 1) | b;
    g_Bp[mat][nh][(((kk * 8 + j4) * 32) + lane) * 4 + c] = __uint_as_float(f2tf(x));
}

__global__ void kSetup(const float* __restrict__ w1,
                       const float* __restrict__ b1,
                       const float* __restrict__ W3,
                       const float* __restrict__ W3b,
                       const float* __restrict__ W4) {
    __shared__ float w1s[H], b1s[H], tsh[H];
    __shared__ int rks[H];
    int h = threadIdx.x, j = blockIdx.x;
    float w = w1[h], b = b1[h];
    w1s[h] = w; b1s[h] = b;
    float t = (w != 0.0f) ? (-b / w) : __int_as_float(0x7f800000);
    tsh[h] = t;
    __syncthreads();
    int r = 0;
    #pragma unroll 8
    for (int k = 0; k < H; ++k) {
        float tk = tsh[k];
        r += (tk < t) || (tk == t && k < h);
    }
    rks[h] = r;
    if (j == 0) g_thr[r] = t;
    __syncthreads();

    float a = 0.0f, c = W3b[h];
    const float* row = W3 + h * 384;   // W3a = cols [0,128)
    for (int k = 0; k < H; ++k) {
        float wk = w1s[k], bk = b1s[k];
        bool act = (wk > 0.0f) ? (rks[k] < j)
                 : (wk < 0.0f) ? (rks[k] >= j)
                               : (bk > 0.0f);
        if (act) {
            float m = row[k];
            a = fmaf(m, wk, a);
            c = fmaf(m, bk, c);
        }
    }
    // planar AC row: A at [0,128), C at [128,256)
    g_AC[j * 256 + h]       = __float2half_rn(a);
    g_AC[j * 256 + 128 + h] = __float2half_rn(c);

    // pack B row k=j: interleaved cols {2h: P3-weight, 2h+1: P4-weight}
    if (j < H) {
        bput(0, j, 2 * h,     W3[h * 384 + 128 + j]);
        bput(0, j, 2 * h + 1, W4[h * 256 + j]);
        bput(1, j, 2 * h,     W3[h * 384 + 256 + j]);
        bput(1, j, 2 * h + 1, W4[h * 256 + 128 + j]);
    }
}

// ---------------- K0d: segment offsets by boundary scatter ----------------
__global__ void kbounds2(const int* __restrict__ seg, int E, int T) {
    int i = blockIdx.x * blockDim.x + threadIdx.x;
    if (i >= E) return;
    int s = __ldg(&seg[i]);
    int sp = (i == 0) ? -1 : __ldg(&seg[i - 1]);
    for (int t = sp + 1; t <= s; ++t) g_off[t] = i;
    if (i == E - 1)
        for (int t = s + 1; t <= T; ++t) g_off[t] = E;
}

// ---------------- K1: tf32 mma.sync projection GEMM ----------------
#define AS 132
__global__ void __launch_bounds__(256, 2)
kgemm(const float* __restrict__ ent_emb, const float* __restrict__ rel_emb,
      const float* __restrict__ W4b, int n_ent, int nt_ent) {
    extern __shared__ float Asm[];   // [128][AS] tf32-converted A tile
    int tid = threadIdx.x, lane = tid & 31, wid = tid >> 5;
    int g = lane >> 2, t = lane & 3;
    int bx = blockIdx.x;
    int mt = bx >> 1, nh = bx & 1;
    bool isrel = (mt >= nt_ent);
    int m0 = (isrel ? mt - nt_ent : mt) * MTILE;
    const float* emb = isrel ? rel_emb : ent_emb;
    int mlim = isrel ? NREL : n_ent;
    const float4* Bp4 = (const float4*)g_Bp[isrel ? 1 : 0][nh];

    #pragma unroll
    for (int i = 0; i < 16; ++i) {
        int e = i * 1024 + tid * 4;
        int r = e >> 7, c = e & 127;
        float4 v = make_float4(0.f, 0.f, 0.f, 0.f);
        if (m0 + r < mlim)
            v = __ldg((const float4*)(emb + (size_t)(m0 + r) * H + c));
        float4 o;
        o.x = __uint_as_float(f2tf(v.x));
        o.y = __uint_as_float(f2tf(v.y));
        o.z = __uint_as_float(f2tf(v.z));
        o.w = __uint_as_float(f2tf(v.w));
        *(float4*)&Asm[r * AS + c] = o;
    }
    __syncthreads();

    float acc[16][4];
    #pragma unroll
    for (int nt = 0; nt < 16; ++nt)
        #pragma unroll
        for (int q = 0; q < 4; ++q) acc[nt][q] = 0.0f;

    int msub = wid * 16;
    #pragma unroll
    for (int kk = 0; kk < 16; ++kk) {
        int k0 = kk * 8;
        uint32_t a0 = __float_as_uint(Asm[(msub + g) * AS + k0 + t]);
        uint32_t a1 = __float_as_uint(Asm[(msub + g + 8) * AS + k0 + t]);
        uint32_t a2 = __float_as_uint(Asm[(msub + g) * AS + k0 + t + 4]);
        uint32_t a3 = __float_as_uint(Asm[(msub + g + 8) * AS + k0 + t + 4]);
        float4 bv[8];
        #pragma unroll
        for (int j4 = 0; j4 < 8; ++j4)
            bv[j4] = __ldg(&Bp4[(kk * 8 + j4) * 32 + lane]);
        #pragma unroll
        for (int nt = 0; nt < 16; ++nt) {
            uint32_t b0 = __float_as_uint((nt & 1) ? bv[nt >> 1].z : bv[nt >> 1].x);
            uint32_t b1 = __float_as_uint((nt & 1) ? bv[nt >> 1].w : bv[nt >> 1].y);
            asm volatile(
                "mma.sync.aligned.m16n8k8.row.col.f32.tf32.tf32.f32 "
                "{%0,%1,%2,%3}, {%4,%5,%6,%7}, {%8,%9}, {%0,%1,%2,%3};"
                : "+f"(acc[nt][0]), "+f"(acc[nt][1]), "+f"(acc[nt][2]), "+f"(acc[nt][3])
                : "r"(a0), "r"(a1), "r"(a2), "r"(a3), "r"(b0), "r"(b1));
        }
    }

    // planar epilogue: P3 at row+2h, P4 at row+256+2h (rows of 512B)
    char* dst = (char*)(isrel ? g_Pr : g_Ps);
    int m = m0 + msub + g;
    #pragma unroll
    for (int nt = 0; nt < 16; ++nt) {
        int h = nh * 64 + nt * 4 + t;
        float bias = isrel ? __ldg(&W4b[h]) : 0.0f;
        *(__half*)(dst + (size_t)m * 512 + h * 2)             = __float2half_rn(acc[nt][0]);
        *(__half*)(dst + (size_t)m * 512 + 256 + h * 2)       = __float2half_rn(acc[nt][1] + bias);
        *(__half*)(dst + (size_t)(m + 8) * 512 + h * 2)       = __float2half_rn(acc[nt][2]);
        *(__half*)(dst + (size_t)(m + 8) * 512 + 256 + h * 2) = __float2half_rn(acc[nt][3] + bias);
    }
}

// ---------------- K2: SIMD-fp16, 1 warp/edge, 4 edge-teams, planar tables ------
__global__ void __launch_bounds__(128)
kedge(const int* __restrict__ nent,
      const int* __restrict__ nrel,
      const float* __restrict__ natt,
      const float* __restrict__ self_att,
      const int* __restrict__ s_ids,
      const int* __restrict__ r_ids,
      const float* __restrict__ ent_embeds,
      const float* __restrict__ rel_embeds,
      const float* __restrict__ w1,
      const float* __restrict__ b1,
      float* __restrict__ out,
      int L, int T) {
    __shared__ float thr_sm[H];
    __shared__ int   off_s[SPB + 1];
    __shared__ int4  q_sm[128];              // {ent*512, rel*512, pos*512, att2 half2}
    __shared__ uint4 red_sm[3][SPB][32];     // teams 1-3 partials {aE0,aE1,aS0,aS1}
    int tid = threadIdx.x;
    int lane = tid & 31, team = tid >> 5;
    int l8 = lane * 8;                       // byte offset of 4 halfs within a 256B plane
    int t0 = blockIdx.x * SPB;
    thr_sm[tid] = g_thr[tid];
    if (tid <= SPB) off_s[tid] = g_off[t0 + tid];
    __syncthreads();
    int base = off_s[0], end = off_s[SPB];

    const __half2 z2 = __float2half2_rn(0.0f);
    __half2 aE[SPB][2], aS[SPB][2];
    #pragma unroll
    for (int s = 0; s < SPB; ++s) {
        aE[s][0] = z2; aE[s][1] = z2; aS[s][0] = z2; aS[s][1] = z2;
    }

    for (int cs = base; cs < end; cs += 128) {
        int m = min(128, end - cs);
        if (tid < m) {
            int   ent = __ldg(&nent[cs + tid]);
            int   rel = __ldg(&nrel[cs + tid]);
            float att = __ldg(&natt[cs + tid]);
            int pos = 0;
            #pragma unroll
            for (int w = 64; w >= 1; w >>= 1)
                if (thr_sm[pos + w - 1] < att) pos += w;
            unsigned ab = __half_as_ushort(__float2half_rn(att));
            q_sm[tid] = make_int4(ent * 512, rel * 512, pos * 512,
                                  (int)(ab | (ab << 16)));
        }
        __syncthreads();
        #pragma unroll
        for (int s = 0; s < SPB; ++s) {
            int lo = max(off_s[s], cs) - cs;
            int hi = min(off_s[s + 1], cs + m) - cs;
            for (int i = lo + team; i < hi; i += 4) {
                int4 q = q_sm[i];
                const char* ps = (const char*)g_Ps + (unsigned)(q.x + l8);
                const char* pr = (const char*)g_Pr + (unsigned)(q.y + l8);
                const char* ac = (const char*)g_AC + (unsigned)(q.z + l8);
                uint2 p3s = __ldg((const uint2*)ps);
                uint2 p4s = __ldg((const uint2*)(ps + 256));
                uint2 p3r = __ldg((const uint2*)pr);
                uint2 p4r = __ldg((const uint2*)(pr + 256));
                uint2 av  = __ldg((const uint2*)ac);
                uint2 cv  = __ldg((const uint2*)(ac + 256));
                __half2 att2 = *(__half2*)&q.w;
                // E channel (h = 4*lane .. 4*lane+3)
                __half2 s0 = __hadd2(*(__half2*)&p3s.x, *(__half2*)&p3r.x);
                __half2 s1 = __hadd2(*(__half2*)&p3s.y, *(__half2*)&p3r.y);
                __half2 w0 = __hfma2(att2, *(__half2*)&av.x, *(__half2*)&cv.x);
                __half2 w1_ = __hfma2(att2, *(__half2*)&av.y, *(__half2*)&cv.y);
                aE[s][0] = __hadd2(aE[s][0], __hmax2(__hadd2(s0, w0), z2));
                aE[s][1] = __hadd2(aE[s][1], __hmax2(__hadd2(s1, w1_), z2));
                // S channel
                __half2 u0 = __hadd2(*(__half2*)&p4s.x, *(__half2*)&p4r.x);
                __half2 u1 = __hadd2(*(__half2*)&p4s.y, *(__half2*)&p4r.y);
                aS[s][0] = __hadd2(aS[s][0], __hmax2(u0, z2));
                aS[s][1] = __hadd2(aS[s][1], __hmax2(u1, z2));
            }
        }
        __syncthreads();
    }

    // cross-team reduction
    if (team >= 1) {
        #pragma unroll
        for (int s = 0; s < SPB; ++s) {
            red_sm[team - 1][s][lane] = make_uint4(
                *(unsigned*)&aE[s][0], *(unsigned*)&aE[s][1],
                *(unsigned*)&aS[s][0], *(unsigned*)&aS[s][1]);
        }
    }
    __syncthreads();

    if (team == 0) {
        float4 wv = __ldg((const float4*)&w1[4 * lane]);
        float4 bv = __ldg((const float4*)&b1[4 * lane]);
        #pragma unroll
        for (int s = 0; s < SPB; ++s) {
            uint4 r0 = red_sm[0][s][lane];
            uint4 r1 = red_sm[1][s][lane];
            uint4 r2 = red_sm[2][s][lane];
            __half2 e0 = __hadd2(__hadd2(aE[s][0], *(__half2*)&r0.x),
                                 __hadd2(*(__half2*)&r1.x, *(__half2*)&r2.x));
            __half2 e1 = __hadd2(__hadd2(aE[s][1], *(__half2*)&r0.y),
                                 __hadd2(*(__half2*)&r1.y, *(__half2*)&r2.y));
            __half2 s0 = __hadd2(__hadd2(aS[s][0], *(__half2*)&r0.z),
                                 __hadd2(*(__half2*)&r1.z, *(__half2*)&r2.z));
            __half2 s1 = __hadd2(__hadd2(aS[s][1], *(__half2*)&r0.w),
                                 __hadd2(*(__half2*)&r1.w, *(__half2*)&r2.w));
            int t = t0 + s;
            float inv = 1.0f / fmaxf((float)(off_s[s + 1] - off_s[s]), 1.0f);
            float2 fe0 = __half22float2(e0), fe1 = __half22float2(e1);
            float2 fs0 = __half22float2(s0), fs1 = __half22float2(s1);
            float4 me = make_float4(fe0.x * inv, fe0.y * inv, fe1.x * inv, fe1.y * inv);
            float4 ms = make_float4(fs0.x * inv, fs0.y * inv, fs1.x * inv, fs1.y * inv);
            int b = t / L;
            float4 es = __ldg((const float4*)&ent_embeds[(size_t)__ldg(&s_ids[b]) * H + 4 * lane]);
            float4 er = __ldg((const float4*)&rel_embeds[(size_t)__ldg(&r_ids[b]) * H + 4 * lane]);
            float sa = __ldg(&self_att[t]);
            float4 sae = make_float4(fmaxf(fmaf(sa, wv.x, bv.x), 0.0f),
                                     fmaxf(fmaf(sa, wv.y, bv.y), 0.0f),
                                     fmaxf(fmaf(sa, wv.z, bv.z), 0.0f),
                                     fmaxf(fmaf(sa, wv.w, bv.w), 0.0f));
            float* out1 = out + (size_t)t * 3 * H;
            float* out2 = out + (size_t)T * 3 * H + (size_t)t * 3 * H;
            *(float4*)&out1[4 * lane]         = es;
            *(float4*)&out1[H + 4 * lane]     = er;
            *(float4*)&out1[2 * H + 4 * lane] = ms;
            *(float4*)&out2[4 * lane]         = sae;
            *(float4*)&out2[H + 4 * lane]     = es;
            *(float4*)&out2[2 * H + 4 * lane] = me;
        }
    }
}

// ---------------- launch ----------------
extern "C" void kernel_launch(void* const* d_in, const int* in_sizes, int n_in,
                              void* d_out, int out_size) {
    const int*   nbr_ent  = (const int*)  d_in[0];
    const int*   nbr_rel  = (const int*)  d_in[1];
    const float* nbr_att  = (const float*)d_in[2];
    const int*   seg_ids  = (const int*)  d_in[3];
    const float* self_att = (const float*)d_in[4];
    const int*   s_ids    = (const int*)  d_in[5];
    const int*   r_ids    = (const int*)  d_in[6];
    const float* ent_emb  = (const float*)d_in[7];
    const float* rel_emb  = (const float*)d_in[8];
    const float* W1w      = (const float*)d_in[9];
    const float* W1b      = (const float*)d_in[10];
    const float* W3w      = (const float*)d_in[11];
    const float* W3b      = (const float*)d_in[12];
    const float* W4w      = (const float*)d_in[13];
    const float* W4b      = (const float*)d_in[14];

    int E = in_sizes[0];
    int B = in_sizes[5];
    int L = in_sizes[4] / B;
    int T = B * L;
    int nent = in_sizes[7] / H;   // 40000
    int nrel = in_sizes[8] / H;   // 256

    int asm_bytes = 128 * AS * 4;   // 67584
    cudaFuncSetAttribute(kgemm, cudaFuncAttributeMaxDynamicSharedMemorySize, asm_bytes);

    kSetup<<<NJ, H>>>(W1w, W1b, W3w, W3b, W4w);
    kbounds2<<<(E + 255) / 256, 256>>>(seg_ids, E, T);

    int nt_ent = (nent + MTILE - 1) / MTILE;          // 313
    int nt_tot = nt_ent + NREL / MTILE;               // 315
    kgemm<<<nt_tot * 2, 256, asm_bytes>>>(ent_emb, rel_emb, W4b, nent, nt_ent);

    kedge<<<T / SPB, H>>>(nbr_ent, nbr_rel, nbr_att, self_att,
                          s_ids, r_ids, ent_emb, rel_emb, W1w, W1b,
                          (float*)d_out, L, T);
}

// round 15
// speedup vs baseline: 1.1338x; 1.1338x over previous
#include <cuda_runtime.h>
#include <cuda_fp16.h>
#include <cstdint>

#define H     128
#define NENT  40000
#define NREL  256
#define NJ    129     // 129 att-intervals (128 breakpoints)
#define TMAX  10241
#define SPB   4       // segments per kedge block
#define MTILE 128

// ---------------- scratch (device globals; no allocation) ----------------
// PLANAR rows (512B each): [P3 halfs x128 | P4 halfs x128]; AC: [A x128 | C x128]
__device__ __half g_Ps[(NENT + MTILE) * 256];
__device__ __half g_Pr[NREL * 256];
__device__ __half g_AC[NJ * 256];
__device__ float  g_thr[H];                  // sorted breakpoints
__device__ int    g_off[TMAX];               // segment start offsets
// B in tf32, pre-packed in per-lane mma-fragment order:
__device__ float  g_Bp[2][2][16 * 8 * 32 * 4];

__device__ __forceinline__ uint32_t f2tf(float x) {
    uint32_t r;
    asm("cvt.rna.tf32.f32 %0, %1;" : "=r"(r) : "f"(x));
    return r;
}

// ---------------- K0: fused setup (NJ=129 blocks x 128 threads) ----------------
__device__ __forceinline__ void bput(int mat, int k, int n, float x) {
    int nh = n >> 7, nl = n & 127;
    int g = nl & 7, nt = nl >> 3;
    int kk = k >> 3, r = k & 7;
    int b = (r >= 4) ? 1 : 0, t = r & 3;
    int lane = (g << 2) | t;
    int j4 = nt >> 1, c = ((nt & 1) << 1) | b;
    g_Bp[mat][nh][(((kk * 8 + j4) * 32) + lane) * 4 + c] = __uint_as_float(f2tf(x));
}

__global__ void kSetup(const float* __restrict__ w1,
                       const float* __restrict__ b1,
                       const float* __restrict__ W3,
                       const float* __restrict__ W3b,
                       const float* __restrict__ W4) {
    __shared__ float w1s[H], b1s[H], tsh[H];
    __shared__ int rks[H];
    int h = threadIdx.x, j = blockIdx.x;
    float w = w1[h], b = b1[h];
    w1s[h] = w; b1s[h] = b;
    float t = (w != 0.0f) ? (-b / w) : __int_as_float(0x7f800000);
    tsh[h] = t;
    __syncthreads();
    int r = 0;
    #pragma unroll 8
    for (int k = 0; k < H; ++k) {
        float tk = tsh[k];
        r += (tk < t) || (tk == t && k < h);
    }
    rks[h] = r;
    if (j == 0) g_thr[r] = t;
    __syncthreads();

    float a = 0.0f, c = W3b[h];
    const float* row = W3 + h * 384;   // W3a = cols [0,128)
    for (int k = 0; k < H; ++k) {
        float wk = w1s[k], bk = b1s[k];
        bool act = (wk > 0.0f) ? (rks[k] < j)
                 : (wk < 0.0f) ? (rks[k] >= j)
                               : (bk > 0.0f);
        if (act) {
            float m = row[k];
            a = fmaf(m, wk, a);
            c = fmaf(m, bk, c);
        }
    }
    // planar AC row: A at [0,128), C at [128,256)
    g_AC[j * 256 + h]       = __float2half_rn(a);
    g_AC[j * 256 + 128 + h] = __float2half_rn(c);

    // pack B row k=j: interleaved cols {2h: P3-weight, 2h+1: P4-weight}
    if (j < H) {
        bput(0, j, 2 * h,     W3[h * 384 + 128 + j]);
        bput(0, j, 2 * h + 1, W4[h * 256 + j]);
        bput(1, j, 2 * h,     W3[h * 384 + 256 + j]);
        bput(1, j, 2 * h + 1, W4[h * 256 + 128 + j]);
    }
}

// ---------------- K0d: segment offsets by boundary scatter ----------------
__global__ void kbounds2(const int* __restrict__ seg, int E, int T) {
    int i = blockIdx.x * blockDim.x + threadIdx.x;
    if (i >= E) return;
    int s = __ldg(&seg[i]);
    int sp = (i == 0) ? -1 : __ldg(&seg[i - 1]);
    for (int t = sp + 1; t <= s; ++t) g_off[t] = i;
    if (i == E - 1)
        for (int t = s + 1; t <= T; ++t) g_off[t] = E;
}

// ---------------- K1: tf32 mma.sync projection GEMM ----------------
#define AS 132
__global__ void __launch_bounds__(256, 2)
kgemm(const float* __restrict__ ent_emb, const float* __restrict__ rel_emb,
      const float* __restrict__ W4b, int n_ent, int nt_ent) {
    extern __shared__ float Asm[];   // [128][AS] tf32 A tile; reused as epilogue staging
    int tid = threadIdx.x, lane = tid & 31, wid = tid >> 5;
    int g = lane >> 2, t = lane & 3;
    int bx = blockIdx.x;
    int mt = bx >> 1, nh = bx & 1;
    bool isrel = (mt >= nt_ent);
    int m0 = (isrel ? mt - nt_ent : mt) * MTILE;
    const float* emb = isrel ? rel_emb : ent_emb;
    int mlim = isrel ? NREL : n_ent;
    const float4* Bp4 = (const float4*)g_Bp[isrel ? 1 : 0][nh];

    #pragma unroll
    for (int i = 0; i < 16; ++i) {
        int e = i * 1024 + tid * 4;
        int r = e >> 7, c = e & 127;
        float4 v = make_float4(0.f, 0.f, 0.f, 0.f);
        if (m0 + r < mlim)
            v = __ldg((const float4*)(emb + (size_t)(m0 + r) * H + c));
        float4 o;
        o.x = __uint_as_float(f2tf(v.x));
        o.y = __uint_as_float(f2tf(v.y));
        o.z = __uint_as_float(f2tf(v.z));
        o.w = __uint_as_float(f2tf(v.w));
        *(float4*)&Asm[r * AS + c] = o;
    }
    __syncthreads();

    float acc[16][4];
    #pragma unroll
    for (int nt = 0; nt < 16; ++nt)
        #pragma unroll
        for (int q = 0; q < 4; ++q) acc[nt][q] = 0.0f;

    int msub = wid * 16;
    #pragma unroll
    for (int kk = 0; kk < 16; ++kk) {
        int k0 = kk * 8;
        uint32_t a0 = __float_as_uint(Asm[(msub + g) * AS + k0 + t]);
        uint32_t a1 = __float_as_uint(Asm[(msub + g + 8) * AS + k0 + t]);
        uint32_t a2 = __float_as_uint(Asm[(msub + g) * AS + k0 + t + 4]);
        uint32_t a3 = __float_as_uint(Asm[(msub + g + 8) * AS + k0 + t + 4]);
        float4 bv[8];
        #pragma unroll
        for (int j4 = 0; j4 < 8; ++j4)
            bv[j4] = __ldg(&Bp4[(kk * 8 + j4) * 32 + lane]);
        #pragma unroll
        for (int nt = 0; nt < 16; ++nt) {
            uint32_t b0 = __float_as_uint((nt & 1) ? bv[nt >> 1].z : bv[nt >> 1].x);
            uint32_t b1 = __float_as_uint((nt & 1) ? bv[nt >> 1].w : bv[nt >> 1].y);
            asm volatile(
                "mma.sync.aligned.m16n8k8.row.col.f32.tf32.tf32.f32 "
                "{%0,%1,%2,%3}, {%4,%5,%6,%7}, {%8,%9}, {%0,%1,%2,%3};"
                : "+f"(acc[nt][0]), "+f"(acc[nt][1]), "+f"(acc[nt][2]), "+f"(acc[nt][3])
                : "r"(a0), "r"(a1), "r"(a2), "r"(a3), "r"(b0), "r"(b1));
        }
    }
    __syncthreads();   // all A reads done; reuse Asm as compact half staging [128][128]

    // stage ONLY this block's columns: row layout [P3 local h x64 | P4 local h x64]
    __half* Hsm = (__half*)Asm;
    int m = msub + g;
    #pragma unroll
    for (int nt = 0; nt < 16; ++nt) {
        int hl = nt * 4 + t;                 // local h: 0..63
        float bias = isrel ? __ldg(&W4b[nh * 64 + hl]) : 0.0f;
        Hsm[m * 128 + hl]            = __float2half_rn(acc[nt][0]);
        Hsm[m * 128 + 64 + hl]       = __float2half_rn(acc[nt][1] + bias);
        Hsm[(m + 8) * 128 + hl]      = __float2half_rn(acc[nt][2]);
        Hsm[(m + 8) * 128 + 64 + hl] = __float2half_rn(acc[nt][3] + bias);
    }
    __syncthreads();

    // coalesced copy of OWNED bytes only: per row two 128B segments
    // (plane0 at row*512 + nh*128, plane1 at row*512 + 256 + nh*128)
    {
        char* dstb = (char*)(isrel ? g_Pr : g_Ps) + (size_t)m0 * 512 + nh * 128;
        const uint4* src = (const uint4*)Hsm;   // 128 rows x 16 uint4
        #pragma unroll
        for (int i = tid; i < 2048; i += 256) {
            int rowm = i >> 4, seg = (i >> 3) & 1, w = i & 7;
            *(uint4*)(dstb + (size_t)rowm * 512 + seg * 256 + w * 16) = src[i];
        }
    }
}

// ---------------- K2: SIMD-fp16, 1 warp/edge, 4 edge-teams, planar tables ------
__global__ void __launch_bounds__(128)
kedge(const int* __restrict__ nent,
      const int* __restrict__ nrel,
      const float* __restrict__ natt,
      const float* __restrict__ self_att,
      const int* __restrict__ s_ids,
      const int* __restrict__ r_ids,
      const float* __restrict__ ent_embeds,
      const float* __restrict__ rel_embeds,
      const float* __restrict__ w1,
      const float* __restrict__ b1,
      float* __restrict__ out,
      int L, int T) {
    __shared__ float thr_sm[H];
    __shared__ int   off_s[SPB + 1];
    __shared__ int4  q_sm[128];              // {ent*512, rel*512, pos*512, att2 half2}
    __shared__ uint4 red_sm[3][SPB][32];     // teams 1-3 partials {aE0,aE1,aS0,aS1}
    int tid = threadIdx.x;
    int lane = tid & 31, team = tid >> 5;
    int l8 = lane * 8;                       // byte offset of 4 halfs within a 256B plane
    int t0 = blockIdx.x * SPB;
    thr_sm[tid] = g_thr[tid];
    if (tid <= SPB) off_s[tid] = g_off[t0 + tid];
    __syncthreads();
    int base = off_s[0], end = off_s[SPB];

    const __half2 z2 = __float2half2_rn(0.0f);
    __half2 aE[SPB][2], aS[SPB][2];
    #pragma unroll
    for (int s = 0; s < SPB; ++s) {
        aE[s][0] = z2; aE[s][1] = z2; aS[s][0] = z2; aS[s][1] = z2;
    }

    for (int cs = base; cs < end; cs += 128) {
        int m = min(128, end - cs);
        if (tid < m) {
            int   ent = __ldg(&nent[cs + tid]);
            int   rel = __ldg(&nrel[cs + tid]);
            float att = __ldg(&natt[cs + tid]);
            int pos = 0;
            #pragma unroll
            for (int w = 64; w >= 1; w >>= 1)
                if (thr_sm[pos + w - 1] < att) pos += w;
            unsigned ab = __half_as_ushort(__float2half_rn(att));
            q_sm[tid] = make_int4(ent * 512, rel * 512, pos * 512,
                                  (int)(ab | (ab << 16)));
        }
        __syncthreads();
        #pragma unroll
        for (int s = 0; s < SPB; ++s) {
            int lo = max(off_s[s], cs) - cs;
            int hi = min(off_s[s + 1], cs + m) - cs;
            #pragma unroll 2
            for (int i = lo + team; i < hi; i += 4) {
                int4 q = q_sm[i];
                const char* ps = (const char*)g_Ps + (unsigned)(q.x + l8);
                const char* pr = (const char*)g_Pr + (unsigned)(q.y + l8);
                const char* ac = (const char*)g_AC + (unsigned)(q.z + l8);
                uint2 p3s = __ldg((const uint2*)ps);
                uint2 p4s = __ldg((const uint2*)(ps + 256));
                uint2 p3r = __ldg((const uint2*)pr);
                uint2 p4r = __ldg((const uint2*)(pr + 256));
                uint2 av  = __ldg((const uint2*)ac);
                uint2 cv  = __ldg((const uint2*)(ac + 256));
                __half2 att2 = *(__half2*)&q.w;
                __half2 s0 = __hadd2(*(__half2*)&p3s.x, *(__half2*)&p3r.x);
                __half2 s1 = __hadd2(*(__half2*)&p3s.y, *(__half2*)&p3r.y);
                __half2 w0 = __hfma2(att2, *(__half2*)&av.x, *(__half2*)&cv.x);
                __half2 w1_ = __hfma2(att2, *(__half2*)&av.y, *(__half2*)&cv.y);
                aE[s][0] = __hadd2(aE[s][0], __hmax2(__hadd2(s0, w0), z2));
                aE[s][1] = __hadd2(aE[s][1], __hmax2(__hadd2(s1, w1_), z2));
                __half2 u0 = __hadd2(*(__half2*)&p4s.x, *(__half2*)&p4r.x);
                __half2 u1 = __hadd2(*(__half2*)&p4s.y, *(__half2*)&p4r.y);
                aS[s][0] = __hadd2(aS[s][0], __hmax2(u0, z2));
                aS[s][1] = __hadd2(aS[s][1], __hmax2(u1, z2));
            }
        }
        __syncthreads();
    }

    // cross-team reduction
    if (team >= 1) {
        #pragma unroll
        for (int s = 0; s < SPB; ++s) {
            red_sm[team - 1][s][lane] = make_uint4(
                *(unsigned*)&aE[s][0], *(unsigned*)&aE[s][1],
                *(unsigned*)&aS[s][0], *(unsigned*)&aS[s][1]);
        }
    }
    __syncthreads();

    if (team == 0) {
        float4 wv = __ldg((const float4*)&w1[4 * lane]);
        float4 bv = __ldg((const float4*)&b1[4 * lane]);
        #pragma unroll
        for (int s = 0; s < SPB; ++s) {
            uint4 r0 = red_sm[0][s][lane];
            uint4 r1 = red_sm[1][s][lane];
            uint4 r2 = red_sm[2][s][lane];
            __half2 e0 = __hadd2(__hadd2(aE[s][0], *(__half2*)&r0.x),
                                 __hadd2(*(__half2*)&r1.x, *(__half2*)&r2.x));
            __half2 e1 = __hadd2(__hadd2(aE[s][1], *(__half2*)&r0.y),
                                 __hadd2(*(__half2*)&r1.y, *(__half2*)&r2.y));
            __half2 s0 = __hadd2(__hadd2(aS[s][0], *(__half2*)&r0.z),
                                 __hadd2(*(__half2*)&r1.z, *(__half2*)&r2.z));
            __half2 s1 = __hadd2(__hadd2(aS[s][1], *(__half2*)&r0.w),
                                 __hadd2(*(__half2*)&r1.w, *(__half2*)&r2.w));
            int t = t0 + s;
            float inv = 1.0f / fmaxf((float)(off_s[s + 1] - off_s[s]), 1.0f);
            float2 fe0 = __half22float2(e0), fe1 = __half22float2(e1);
            float2 fs0 = __half22float2(s0), fs1 = __half22float2(s1);
            float4 me = make_float4(fe0.x * inv, fe0.y * inv, fe1.x * inv, fe1.y * inv);
            float4 ms = make_float4(fs0.x * inv, fs0.y * inv, fs1.x * inv, fs1.y * inv);
            int b = t / L;
            float4 es = __ldg((const float4*)&ent_embeds[(size_t)__ldg(&s_ids[b]) * H + 4 * lane]);
            float4 er = __ldg((const float4*)&rel_embeds[(size_t)__ldg(&r_ids[b]) * H + 4 * lane]);
            float sa = __ldg(&self_att[t]);
            float4 sae = make_float4(fmaxf(fmaf(sa, wv.x, bv.x), 0.0f),
                                     fmaxf(fmaf(sa, wv.y, bv.y), 0.0f),
                                     fmaxf(fmaf(sa, wv.z, bv.z), 0.0f),
                                     fmaxf(fmaf(sa, wv.w, bv.w), 0.0f));
            float* out1 = out + (size_t)t * 3 * H;
            float* out2 = out + (size_t)T * 3 * H + (size_t)t * 3 * H;
            *(float4*)&out1[4 * lane]         = es;
            *(float4*)&out1[H + 4 * lane]     = er;
            *(float4*)&out1[2 * H + 4 * lane] = ms;
            *(float4*)&out2[4 * lane]         = sae;
            *(float4*)&out2[H + 4 * lane]     = es;
            *(float4*)&out2[2 * H + 4 * lane] = me;
        }
    }
}

// ---------------- launch ----------------
extern "C" void kernel_launch(void* const* d_in, const int* in_sizes, int n_in,
                              void* d_out, int out_size) {
    const int*   nbr_ent  = (const int*)  d_in[0];
    const int*   nbr_rel  = (const int*)  d_in[1];
    const float* nbr_att  = (const float*)d_in[2];
    const int*   seg_ids  = (const int*)  d_in[3];
    const float* self_att = (const float*)d_in[4];
    const int*   s_ids    = (const int*)  d_in[5];
    const int*   r_ids    = (const int*)  d_in[6];
    const float* ent_emb  = (const float*)d_in[7];
    const float* rel_emb  = (const float*)d_in[8];
    const float* W1w      = (const float*)d_in[9];
    const float* W1b      = (const float*)d_in[10];
    const float* W3w      = (const float*)d_in[11];
    const float* W3b      = (const float*)d_in[12];
    const float* W4w      = (const float*)d_in[13];
    const float* W4b      = (const float*)d_in[14];

    int E = in_sizes[0];
    int B = in_sizes[5];
    int L = in_sizes[4] / B;
    int T = B * L;
    int nent = in_sizes[7] / H;   // 40000
    int nrel = in_sizes[8] / H;   // 256

    int asm_bytes = 128 * AS * 4;   // 67584
    cudaFuncSetAttribute(kgemm, cudaFuncAttributeMaxDynamicSharedMemorySize, asm_bytes);

    kSetup<<<NJ, H>>>(W1w, W1b, W3w, W3b, W4w);
    kbounds2<<<(E + 255) / 256, 256>>>(seg_ids, E, T);

    int nt_ent = (nent + MTILE - 1) / MTILE;          // 313
    int nt_tot = nt_ent + NREL / MTILE;               // 315
    kgemm<<<nt_tot * 2, 256, asm_bytes>>>(ent_emb, rel_emb, W4b, nent, nt_ent);

    kedge<<<T / SPB, H>>>(nbr_ent, nbr_rel, nbr_att, self_att,
                          s_ids, r_ids, ent_emb, rel_emb, W1w, W1b,
                          (float*)d_out, L, T);
}